// round 15
// baseline (speedup 1.0000x reference)
#include <cuda_runtime.h>
#include <math.h>

#define TT 128
#define BB 128
#define ZD 64
#define AD 64
#define KK 32
#define SD 68
#define TB (TT*BB)

typedef unsigned long long ull;

// ---------------- device scratch (allocation-free rule) ----------------
__device__ float g_Q[ZD*ZD];
__device__ float g_R[AD*AD];
__device__ float g_w[TB*KK];
__device__ float g_A[(size_t)TB*4096];
__device__ float g_C[(size_t)TB*4096];
__device__ float g_AC[(size_t)TB*4096];   // A*covt per (t,b)
__device__ float g_Pn[(size_t)TB*4096];   // predicted covariance per (t,b)
__device__ float g_J[(size_t)TB*4096];    // Pn^-1 per (t,b)  (matrix-free J)
__device__ float g_fm[TB*ZD];
__device__ float g_mp0[BB*ZD];

// ---------------- f32x2 helpers ----------------
__device__ __forceinline__ ull dup2(float a){
    ull d; asm("mov.b64 %0, {%1, %1};" : "=l"(d) : "f"(a)); return d;
}
__device__ __forceinline__ ull fma2(ull a, ull b, ull c){
    ull d; asm("fma.rn.f32x2 %0, %1, %2, %3;" : "=l"(d) : "l"(a), "l"(b), "l"(c)); return d;
}
__device__ __forceinline__ ull add2(ull a, ull b){
    ull d; asm("add.rn.f32x2 %0, %1, %2;" : "=l"(d) : "l"(a), "l"(b)); return d;
}
__device__ __forceinline__ float2 unpk(ull v){
    float2 r; asm("mov.b64 {%0, %1}, %2;" : "=f"(r.x), "=f"(r.y) : "l"(v)); return r;
}

// ======== 512-thread split-K mm: O = A @ B (+Add) [smem, stride SD] ========
// Half h = tid>>8 sums k in [32h, 32h+32) with 4x4 f32x2 tiles (lt = tid&255).
// Half 1 stores partials to red; half 0 reduces + epilogue. Crossbar traffic
// identical to the 256-thread version; per-thread latency chain halved.
template<bool ADD, bool GST>
__device__ __forceinline__ void mm512_nn(const float* __restrict__ A,
                                         const float* __restrict__ B,
                                         const float* __restrict__ Add,
                                         float* __restrict__ O,
                                         float* __restrict__ G,
                                         float* __restrict__ red,
                                         int lt, int h)
{
    const int tx4 = (lt & 15) << 2;
    const int ty4 = (lt >> 4) << 2;
    const int kb  = h << 5;
    ull acc[4][2];
    #pragma unroll
    for (int i = 0; i < 4; i++){ acc[i][0] = dup2(0.0f); acc[i][1] = dup2(0.0f); }
    #pragma unroll
    for (int k0 = 0; k0 < 32; k0 += 4){
        const float* Ak = A + kb + k0;
        float4 a0 = *(const float4*)(Ak + (ty4+0)*SD);
        float4 a1 = *(const float4*)(Ak + (ty4+1)*SD);
        float4 a2 = *(const float4*)(Ak + (ty4+2)*SD);
        float4 a3 = *(const float4*)(Ak + (ty4+3)*SD);
        const float* Bk = B + (kb + k0)*SD + tx4;
        ulonglong2 b0 = *(const ulonglong2*)(Bk);
        ulonglong2 b1 = *(const ulonglong2*)(Bk + SD);
        ulonglong2 b2 = *(const ulonglong2*)(Bk + 2*SD);
        ulonglong2 b3 = *(const ulonglong2*)(Bk + 3*SD);
        #pragma unroll
        for (int i = 0; i < 4; i++){
            float4 av = (i==0)?a0:((i==1)?a1:((i==2)?a2:a3));
            ull d;
            d = dup2(av.x); acc[i][0]=fma2(d,b0.x,acc[i][0]); acc[i][1]=fma2(d,b0.y,acc[i][1]);
            d = dup2(av.y); acc[i][0]=fma2(d,b1.x,acc[i][0]); acc[i][1]=fma2(d,b1.y,acc[i][1]);
            d = dup2(av.z); acc[i][0]=fma2(d,b2.x,acc[i][0]); acc[i][1]=fma2(d,b2.y,acc[i][1]);
            d = dup2(av.w); acc[i][0]=fma2(d,b3.x,acc[i][0]); acc[i][1]=fma2(d,b3.y,acc[i][1]);
        }
    }
    if (h){
        #pragma unroll
        for (int i = 0; i < 4; i++){
            ulonglong2 st; st.x = acc[i][0]; st.y = acc[i][1];
            *(ulonglong2*)(red + (ty4+i)*SD + tx4) = st;
        }
    }
    __syncthreads();
    if (!h){
        #pragma unroll
        for (int i = 0; i < 4; i++){
            ulonglong2 pr = *(const ulonglong2*)(red + (ty4+i)*SD + tx4);
            ull v0 = add2(acc[i][0], pr.x);
            ull v1 = add2(acc[i][1], pr.y);
            if (ADD){
                ulonglong2 ad = *(const ulonglong2*)(Add + (ty4+i)*SD + tx4);
                v0 = add2(v0, ad.x); v1 = add2(v1, ad.y);
            }
            ulonglong2 st; st.x = v0; st.y = v1;
            *(ulonglong2*)(O + (ty4+i)*SD + tx4) = st;
            if (GST) *(ulonglong2*)(G + (ty4+i)*64 + tx4) = st;
        }
    }
    __syncthreads();
}

// O = Sub - A^T @ B (512 threads split-K); ends synced
__device__ __forceinline__ void mm512_tn_sub(const float* __restrict__ A,
                                             const float* __restrict__ B,
                                             const float* __restrict__ Sub,
                                             float* __restrict__ O,
                                             float* __restrict__ red,
                                             int lt, int h)
{
    const int tx4 = (lt & 15) << 2;
    const int ty4 = (lt >> 4) << 2;
    const int kb  = h << 5;
    ull acc[4][2];
    #pragma unroll
    for (int i = 0; i < 4; i++){ acc[i][0] = dup2(0.0f); acc[i][1] = dup2(0.0f); }
    #pragma unroll 8
    for (int k = 0; k < 32; k++){
        float4 av = *(const float4*)(A + (kb+k)*SD + ty4);
        ulonglong2 bv = *(const ulonglong2*)(B + (kb+k)*SD + tx4);
        ull d;
        d = dup2(av.x); acc[0][0]=fma2(d,bv.x,acc[0][0]); acc[0][1]=fma2(d,bv.y,acc[0][1]);
        d = dup2(av.y); acc[1][0]=fma2(d,bv.x,acc[1][0]); acc[1][1]=fma2(d,bv.y,acc[1][1]);
        d = dup2(av.z); acc[2][0]=fma2(d,bv.x,acc[2][0]); acc[2][1]=fma2(d,bv.y,acc[2][1]);
        d = dup2(av.w); acc[3][0]=fma2(d,bv.x,acc[3][0]); acc[3][1]=fma2(d,bv.y,acc[3][1]);
    }
    if (h){
        #pragma unroll
        for (int i = 0; i < 4; i++){
            ulonglong2 st; st.x = acc[i][0]; st.y = acc[i][1];
            *(ulonglong2*)(red + (ty4+i)*SD + tx4) = st;
        }
    }
    __syncthreads();
    if (!h){
        const ull NEG1 = dup2(-1.0f);
        #pragma unroll
        for (int i = 0; i < 4; i++){
            ulonglong2 pr = *(const ulonglong2*)(red + (ty4+i)*SD + tx4);
            ull s0 = add2(acc[i][0], pr.x);
            ull s1 = add2(acc[i][1], pr.y);
            ulonglong2 sv = *(const ulonglong2*)(Sub + (ty4+i)*SD + tx4);
            ulonglong2 st;
            st.x = fma2(NEG1, s0, sv.x);
            st.y = fma2(NEG1, s1, sv.y);
            *(ulonglong2*)(O + (ty4+i)*SD + tx4) = st;
        }
    }
    __syncthreads();
}

// ======== 512-thread fused GJ solve: M X = RHS (M SPD) — from R7 ==========
// Thread (sr=tid>>3, sc8=(tid&7)*8) holds M[sr][sc8..+7] in m2[4] and
// RHS[sr][sc8..+7] in r2[4]. One barrier/pivot; sign-symmetry recovery.
__device__ __forceinline__ void gj512_solve(ull* m2, ull* r2,
                                            float* __restrict__ prow,  // 2*128
                                            float* __restrict__ scbuf, // 2
                                            const int sr, const int sc8)
{
    #pragma unroll 1
    for (int p = 0; p < 64; p++){
        float* prb = prow + ((p & 1) << 7);
        if (sr == p){
            ulonglong2 s;
            s.x = m2[0]; s.y = m2[1]; *(ulonglong2*)(prb + sc8)     = s;
            s.x = m2[2]; s.y = m2[3]; *(ulonglong2*)(prb + sc8 + 4) = s;
            s.x = r2[0]; s.y = r2[1]; *(ulonglong2*)(prb + 64 + sc8)     = s;
            s.x = r2[2]; s.y = r2[3]; *(ulonglong2*)(prb + 64 + sc8 + 4) = s;
            if ((p >> 3) == (sc8 >> 3)){
                int l = p & 7;
                float2 h = unpk(m2[l >> 1]);
                float pv = (l & 1) ? h.y : h.x;
                scbuf[p & 1] = pv;
                prb[p] = pv + 1.0f;     // augment pivot row at col p
            }
        }
        __syncthreads();
        const float piv = scbuf[p & 1];
        const float pivinv = __frcp_rn(piv);
        const float urow = prb[sr];     // augmented at sr==p
        const float u_ = (sr < p) ? -urow : ((sr == p) ? urow - 2.0f : urow);
        const ull fd = dup2(-(u_ * pivinv));
        ulonglong2 q0 = *(const ulonglong2*)(prb + sc8);
        ulonglong2 q1 = *(const ulonglong2*)(prb + sc8 + 4);
        m2[0] = fma2(fd, q0.x, m2[0]); m2[1] = fma2(fd, q0.y, m2[1]);
        m2[2] = fma2(fd, q1.x, m2[2]); m2[3] = fma2(fd, q1.y, m2[3]);
        ulonglong2 w0 = *(const ulonglong2*)(prb + 64 + sc8);
        ulonglong2 w1 = *(const ulonglong2*)(prb + 64 + sc8 + 4);
        r2[0] = fma2(fd, w0.x, r2[0]); r2[1] = fma2(fd, w0.y, r2[1]);
        r2[2] = fma2(fd, w1.x, r2[2]); r2[3] = fma2(fd, w1.y, r2[3]);
    }
}

// ---------------- kernel 1: Q/R construction ----------------
__global__ void qr_kernel(const float* __restrict__ Lq, const float* __restrict__ Lr){
    __shared__ float sL[64*65];
    const float* L = (blockIdx.x == 0) ? Lq : Lr;
    float* O = (blockIdx.x == 0) ? g_Q : g_R;
    int tid = threadIdx.x;
    for (int i = tid; i < 4096; i += 256) sL[(i>>6)*65 + (i&63)] = L[i];
    __syncthreads();
    for (int e = tid; e < 4096; e += 256){
        int i = e >> 6, j = e & 63;
        float acc = (i == j) ? 1e-3f : 0.0f;
        #pragma unroll 8
        for (int k = 0; k < 64; k++) acc += sL[i*65+k]*sL[j*65+k];
        O[e] = acc;
    }
}

// ---------------- kernel 2: LSTM + softmax weights ----------------
__global__ void __launch_bounds__(128) lstm_kernel(
    const float* __restrict__ x,
    const float* __restrict__ Wih, const float* __restrict__ Whh,
    const float* __restrict__ bih, const float* __restrict__ bhh)
{
    extern __shared__ float sm[];
    float* sWih = sm;                 // 128*65
    float* sWhh = sWih + 128*65;      // 128*33
    float* sx   = sWhh + 128*33;      // 128*64
    float* sh   = sx + 128*64;        // 32
    float* sg   = sh + 32;            // 128
    const int b = blockIdx.x, tid = threadIdx.x;
    for (int i = tid; i < 128*64; i += 128) sWih[(i>>6)*65 + (i&63)] = Wih[i];
    for (int i = tid; i < 128*32; i += 128) sWhh[(i>>5)*33 + (i&31)] = Whh[i];
    for (int i = tid; i < TT*64;  i += 128) sx[i] = x[((i>>6)*BB + b)*64 + (i&63)];
    if (tid < 32) sh[tid] = 0.0f;
    const float bias = bih[tid] + bhh[tid];
    float c = 0.0f;
    __syncthreads();
    for (int t = 0; t < TT; t++){
        float acc = bias;
        const float* wr = sWih + tid*65;
        const float* xr = sx + t*64;
        #pragma unroll 8
        for (int j = 0; j < 64; j++) acc += wr[j]*xr[j];
        const float* hr = sWhh + tid*33;
        #pragma unroll 8
        for (int j = 0; j < 32; j++) acc += hr[j]*sh[j];
        sg[tid] = acc;
        __syncthreads();
        if (tid < 32){
            float ig = 1.0f/(1.0f+expf(-sg[tid]));
            float fg = 1.0f/(1.0f+expf(-sg[32+tid]));
            float gg = tanhf(sg[64+tid]);
            float og = 1.0f/(1.0f+expf(-sg[96+tid]));
            c = fg*c + ig*gg;
            float h = og*tanhf(c);
            sh[tid] = h;
            float m = h;
            for (int o = 16; o; o >>= 1) m = fmaxf(m, __shfl_xor_sync(0xffffffffu, m, o));
            float e = expf(h - m);
            float s = e;
            for (int o = 16; o; o >>= 1) s += __shfl_xor_sync(0xffffffffu, s, o);
            g_w[(t*BB + b)*KK + tid] = e/s;
        }
        __syncthreads();
    }
}

// ---------------- kernel 3: mix A_t, C_t from basis ----------------
__global__ void mix_kernel(const float* __restrict__ AK, const float* __restrict__ CK){
    __shared__ float sB[32*256];
    __shared__ float sw[64*33];
    const int chunk = blockIdx.x;     // 0..15
    const int grp   = blockIdx.y;     // 0..255
    const float* Bsrc = (blockIdx.z == 0) ? AK : CK;
    float* Odst = (blockIdx.z == 0) ? g_A : g_C;
    const int tid = threadIdx.x;      // 256
    for (int i = tid; i < 32*256; i += 256)
        sB[i] = Bsrc[(i>>8)*4096 + chunk*256 + (i&255)];
    for (int i = tid; i < 64*32; i += 256)
        sw[(i>>5)*33 + (i&31)] = g_w[((size_t)grp*64 + (i>>5))*KK + (i&31)];
    __syncthreads();
    const int j = tid;
    for (int tb = 0; tb < 64; tb++){
        float acc = 0.0f;
        const float* wv = sw + tb*33;
        #pragma unroll
        for (int k = 0; k < 32; k++) acc += wv[k]*sB[k*256 + j];
        Odst[(size_t)(grp*64 + tb)*4096 + chunk*256 + j] = acc;
    }
}

// ---------------- kernel 4: Kalman filter (512 threads, split-K mms) ------
__global__ void __launch_bounds__(512, 1) filter_kernel(
    const float* __restrict__ as_,
    const float* __restrict__ init_mean,
    const float* __restrict__ init_cov)
{
    extern __shared__ float sm[];
    float* Qs  = sm;
    float* Rs  = Qs  + 64*SD;
    float* As  = Rs  + 64*SD;
    float* AsT = As  + 64*SD;
    float* Cs  = AsT + 64*SD;
    float* CsT = Cs  + 64*SD;
    float* BP0 = CsT + 64*SD;
    float* BP1 = BP0 + 64*SD;
    float* T1  = BP1 + 64*SD;   // CP, later Acovt
    float* T2  = T1  + 64*SD;   // S, later K^T
    float* T3  = T2  + 64*SD;   // covt
    float* vmean = T3 + 64*SD;
    float* vmt   = vmean + 64;
    float* vmn   = vmt + 64;
    float* vin   = vmn + 64;
    float* vat   = vin + 64;
    float* prow  = vat + 64;    // 256
    float* scb   = prow + 256;  // 2 (+pad)
    const int b = blockIdx.x, tid = threadIdx.x;
    const int lt = tid & 255;
    const int h  = tid >> 8;
    const int sr  = tid >> 3;          // solve row
    const int sc8 = (tid & 7) << 3;    // solve col block

    for (int i = tid; i < 4096; i += 512){
        int rr = i >> 6, cc = i & 63;
        BP0[rr*SD + cc] = init_cov[i];
        Qs[rr*SD + cc]  = g_Q[i];
        Rs[rr*SD + cc]  = g_R[i];
    }
    if (tid < 64) vmean[tid] = init_mean[tid];
    __syncthreads();

    float* P  = BP0;
    float* Pn = BP1;

    for (int t = 0; t < TT; t++){
        const int tb = t*BB + b;

        {   // load step tiles (As, Cs + transposes) and a_t
            const float* gA = g_A + (size_t)tb*4096;
            const float* gC = g_C + (size_t)tb*4096;
            for (int i4 = tid; i4 < 1024; i4 += 512){
                int rr = i4 >> 4, c4 = (i4 & 15) << 2;
                float4 va = *(const float4*)(gA + rr*64 + c4);
                float4 vc = *(const float4*)(gC + rr*64 + c4);
                *(float4*)(As + rr*SD + c4) = va;
                *(float4*)(Cs + rr*SD + c4) = vc;
                AsT[(c4+0)*SD + rr] = va.x; AsT[(c4+1)*SD + rr] = va.y;
                AsT[(c4+2)*SD + rr] = va.z; AsT[(c4+3)*SD + rr] = va.w;
                CsT[(c4+0)*SD + rr] = vc.x; CsT[(c4+1)*SD + rr] = vc.y;
                CsT[(c4+2)*SD + rr] = vc.z; CsT[(c4+3)*SD + rr] = vc.w;
            }
            if (tid < 64) vat[tid] = as_[(size_t)tb*64 + tid];
            __syncthreads();
        }

        mm512_nn<false,false>(Cs, P, 0, T1, 0, T3, lt, h);   // T1 = CP  (red=T3)
        mm512_nn<true ,false>(T1, CsT, Rs, T2, 0, T3, lt, h);// T2 = S   (red=T3)

        if (tid < 64){                                       // vin = a_t - C mean_p
            float acc = 0.0f;
            #pragma unroll 8
            for (int j = 0; j < 64; j++) acc += Cs[tid*SD + j]*vmean[j];
            vin[tid] = vat[tid] - acc;
        }

        // fused solve: K^T = S^-1 CP
        {
            ull m2[4], r2[4];
            ulonglong2 a0 = *(const ulonglong2*)(T2 + sr*SD + sc8);
            ulonglong2 a1 = *(const ulonglong2*)(T2 + sr*SD + sc8 + 4);
            m2[0] = a0.x; m2[1] = a0.y; m2[2] = a1.x; m2[3] = a1.y;
            ulonglong2 c0 = *(const ulonglong2*)(T1 + sr*SD + sc8);
            ulonglong2 c1 = *(const ulonglong2*)(T1 + sr*SD + sc8 + 4);
            r2[0] = c0.x; r2[1] = c0.y; r2[2] = c1.x; r2[3] = c1.y;
            gj512_solve(m2, r2, prow, scb, sr, sc8);
            ulonglong2 s0; s0.x = r2[0]; s0.y = r2[1];
            ulonglong2 s1; s1.x = r2[2]; s1.y = r2[3];
            *(ulonglong2*)(T2 + sr*SD + sc8)     = s0;       // T2 = K^T
            *(ulonglong2*)(T2 + sr*SD + sc8 + 4) = s1;
            __syncthreads();
        }

        if (tid < 64){                                       // mean_t = mean_p + K^T^T vin
            float acc = vmean[tid];
            #pragma unroll 8
            for (int j = 0; j < 64; j++) acc += T2[j*SD + tid]*vin[j];
            vmt[tid] = acc;
            g_fm[(size_t)tb*64 + tid] = acc;
        }

        mm512_tn_sub(T2, T1, P, T3, Pn, lt, h);              // T3 = covt (red=Pn)

        mm512_nn<false,true>(As, T3, 0, T1,                  // T1 = A covt (+ gmem)
                             g_AC + (size_t)tb*4096, Pn, lt, h);

        if (tid < 64){                                       // mean_n = A mean_t
            float acc = 0.0f;
            #pragma unroll 8
            for (int j = 0; j < 64; j++) acc += As[tid*SD + j]*vmt[j];
            vmn[tid] = acc;
            if (t == 0) g_mp0[b*64 + tid] = acc;
        }

        mm512_nn<true,true>(T1, AsT, Qs, Pn,                 // Pn = A covt A^T + Q (+ gmem)
                            g_Pn + (size_t)tb*4096, T3, lt, h);

        if (tid < 64) vmean[tid] = vmn[tid];                 // same-thread write/read
        float* tmp = P; P = Pn; Pn = tmp;
        __syncthreads();
    }
}

// ---------------- kernel 5: Pn^-1 (inverse-only register GJ, R13) ---------
__global__ void __launch_bounds__(256, 4) jinv_kernel(){
    __shared__ float prow[128];
    __shared__ float scb[2];
    const int tb = blockIdx.y*BB + blockIdx.x;
    const int tid = threadIdx.x;
    const int r  = tid >> 2;
    const int cb = (tid & 3) << 4;
    const float* gPn = g_Pn + (size_t)tb*4096;
    ull m2[8];
    #pragma unroll
    for (int u = 0; u < 4; u++){
        ulonglong2 a = *(const ulonglong2*)(gPn + r*64 + cb + 4*u);
        m2[2*u] = a.x; m2[2*u+1] = a.y;
    }
    #pragma unroll 1
    for (int p = 0; p < 64; p++){
        float* prb = prow + ((p & 1) << 6);
        if (r == p){
            ulonglong2 s;
            s.x=m2[0]; s.y=m2[1]; *(ulonglong2*)(prb + cb)      = s;
            s.x=m2[2]; s.y=m2[3]; *(ulonglong2*)(prb + cb + 4)  = s;
            s.x=m2[4]; s.y=m2[5]; *(ulonglong2*)(prb + cb + 8)  = s;
            s.x=m2[6]; s.y=m2[7]; *(ulonglong2*)(prb + cb + 12) = s;
            if ((p >> 4) == (cb >> 4)){
                int l = p & 15;
                float2 h = unpk(m2[l >> 1]);
                float pv = (l & 1) ? h.y : h.x;
                scb[p & 1] = pv;
                prb[p] = pv + 1.0f;
            }
        }
        __syncthreads();
        const float piv = scb[p & 1];
        const float pivinv = __frcp_rn(piv);
        const float urow = prb[r];
        const float u_ = (r < p) ? -urow : ((r == p) ? urow - 2.0f : urow);
        const ull fd = dup2(-(u_ * pivinv));
        ulonglong2 q0 = *(const ulonglong2*)(prb + cb);
        ulonglong2 q1 = *(const ulonglong2*)(prb + cb + 4);
        ulonglong2 q2 = *(const ulonglong2*)(prb + cb + 8);
        ulonglong2 q3 = *(const ulonglong2*)(prb + cb + 12);
        m2[0]=fma2(fd,q0.x,m2[0]); m2[1]=fma2(fd,q0.y,m2[1]);
        m2[2]=fma2(fd,q1.x,m2[2]); m2[3]=fma2(fd,q1.y,m2[3]);
        m2[4]=fma2(fd,q2.x,m2[4]); m2[5]=fma2(fd,q2.y,m2[5]);
        m2[6]=fma2(fd,q3.x,m2[6]); m2[7]=fma2(fd,q3.y,m2[7]);
    }
    float* gJ = g_J + (size_t)tb*4096;
    #pragma unroll
    for (int u = 0; u < 4; u++){
        ulonglong2 s; s.x = m2[2*u]; s.y = m2[2*u+1];
        *(ulonglong2*)(gJ + r*64 + cb + 4*u) = s;
    }
}

// ---------------- kernel 6: RTS smoother, matrix-free J ------------------
__global__ void __launch_bounds__(256) smooth_kernel(float* __restrict__ out)
{
    __shared__ float sP[64*65];   // Pn^-1
    __shared__ float sA[64*65];   // A covt
    __shared__ float sv[64];
    __shared__ float sy[64];
    __shared__ float sms[64];
    __shared__ float smp0[64];
    const int b = blockIdx.x, tid = threadIdx.x;

    if (tid < 64){
        float m = g_fm[(size_t)((TT-1)*BB + b)*64 + tid];
        sms[tid] = m;
        out[(size_t)((TT-1)*BB + b)*64 + tid] = m;
        smp0[tid] = g_mp0[b*64 + tid];
    }
    float4 rp[4], ra[4];
    {
        const float* gP = g_J  + (size_t)((TT-2)*BB + b)*4096;
        const float* gA = g_AC + (size_t)((TT-2)*BB + b)*4096;
        #pragma unroll
        for (int u = 0; u < 4; u++){
            rp[u] = *(const float4*)(gP + (size_t)(tid + 256*u)*4);
            ra[u] = *(const float4*)(gA + (size_t)(tid + 256*u)*4);
        }
    }
    __syncthreads();

    for (int t = TT-2; t >= 0; t--){
        #pragma unroll
        for (int u = 0; u < 4; u++){
            int idx = tid + 256*u;
            int row = idx >> 4, c4 = (idx & 15) << 2;
            sP[row*65 + c4 + 0] = rp[u].x;
            sP[row*65 + c4 + 1] = rp[u].y;
            sP[row*65 + c4 + 2] = rp[u].z;
            sP[row*65 + c4 + 3] = rp[u].w;
            sA[row*65 + c4 + 0] = ra[u].x;
            sA[row*65 + c4 + 1] = ra[u].y;
            sA[row*65 + c4 + 2] = ra[u].z;
            sA[row*65 + c4 + 3] = ra[u].w;
        }
        if (tid < 64) sv[tid] = sms[tid] - smp0[tid];
        __syncthreads();
        if (t > 0){
            const float* gP = g_J  + (size_t)((t-1)*BB + b)*4096;
            const float* gA = g_AC + (size_t)((t-1)*BB + b)*4096;
            #pragma unroll
            for (int u = 0; u < 4; u++){
                rp[u] = *(const float4*)(gP + (size_t)(tid + 256*u)*4);
                ra[u] = *(const float4*)(gA + (size_t)(tid + 256*u)*4);
            }
        }
        if (tid < 64){                       // y = Pn^-1 v
            float acc = 0.0f;
            #pragma unroll 8
            for (int j = 0; j < 64; j++) acc += sP[tid*65 + j]*sv[j];
            sy[tid] = acc;
        }
        __syncthreads();
        if (tid < 64){                       // s = fm + (A covt)^T y
            float acc = g_fm[(size_t)(t*BB + b)*64 + tid];
            #pragma unroll 8
            for (int j = 0; j < 64; j++) acc += sA[j*65 + tid]*sy[j];
            out[(size_t)(t*BB + b)*64 + tid] = acc;
            sms[tid] = acc;
        }
        __syncthreads();
    }
}

// ---------------- launch ----------------
extern "C" void kernel_launch(void* const* d_in, const int* in_sizes, int n_in,
                              void* d_out, int out_size)
{
    const float* as_ = (const float*)d_in[0];
    const float* AK  = (const float*)d_in[1];
    const float* CK  = (const float*)d_in[2];
    const float* Lq  = (const float*)d_in[3];
    const float* Lr  = (const float*)d_in[4];
    const float* Wih = (const float*)d_in[5];
    const float* Whh = (const float*)d_in[6];
    const float* bih = (const float*)d_in[7];
    const float* bhh = (const float*)d_in[8];
    const float* im  = (const float*)d_in[9];
    const float* ic  = (const float*)d_in[10];
    float* out = (float*)d_out;

    const int lstm_smem = (128*65 + 128*33 + 128*64 + 32 + 128)*4;
    const int filt_smem = (11*64*SD + 5*64 + 256 + 8)*4;
    cudaFuncSetAttribute(lstm_kernel,   cudaFuncAttributeMaxDynamicSharedMemorySize, lstm_smem);
    cudaFuncSetAttribute(filter_kernel, cudaFuncAttributeMaxDynamicSharedMemorySize, filt_smem);

    qr_kernel<<<2, 256>>>(Lq, Lr);
    lstm_kernel<<<BB, 128, lstm_smem>>>(as_, Wih, Whh, bih, bhh);
    mix_kernel<<<dim3(16, 256, 2), 256>>>(AK, CK);
    filter_kernel<<<BB, 512, filt_smem>>>(as_, im, ic);
    jinv_kernel<<<dim3(BB, TT-1), 256>>>();
    smooth_kernel<<<BB, 256>>>(out);
}

// round 16
// speedup vs baseline: 1.2557x; 1.2557x over previous
#include <cuda_runtime.h>
#include <math.h>

#define TT 128
#define BB 128
#define ZD 64
#define AD 64
#define KK 32
#define SD 68
#define TB (TT*BB)

typedef unsigned long long ull;

// ---------------- device scratch (allocation-free rule) ----------------
__device__ float g_Q[ZD*ZD];
__device__ float g_R[AD*AD];
__device__ float g_w[TB*KK];
__device__ float g_A[(size_t)TB*4096];
__device__ float g_C[(size_t)TB*4096];
__device__ float g_AC[(size_t)TB*4096];   // A*covt per (t,b)
__device__ float g_Pn[(size_t)TB*4096];   // predicted covariance per (t,b)
__device__ float g_J[(size_t)TB*4096];    // Pn^-1 per (t,b)  (matrix-free J)
__device__ float g_fm[TB*ZD];
__device__ float g_mp0[BB*ZD];

// ---------------- f32x2 helpers ----------------
__device__ __forceinline__ ull dup2(float a){
    ull d; asm("mov.b64 %0, {%1, %1};" : "=l"(d) : "f"(a)); return d;
}
__device__ __forceinline__ ull fma2(ull a, ull b, ull c){
    ull d; asm("fma.rn.f32x2 %0, %1, %2, %3;" : "=l"(d) : "l"(a), "l"(b), "l"(c)); return d;
}
__device__ __forceinline__ ull add2(ull a, ull b){
    ull d; asm("add.rn.f32x2 %0, %1, %2;" : "=l"(d) : "l"(a), "l"(b)); return d;
}
__device__ __forceinline__ float2 unpk(ull v){
    float2 r; asm("mov.b64 {%0, %1}, %2;" : "=f"(r.x), "=f"(r.y) : "l"(v)); return r;
}

// ---------------- mm: O = A @ B (+Add) [all row-major stride SD] ----------
// 256 threads, 4x4 register tiles, f32x2 accumulators. Ends synced.
// GST: also store result to gmem G with row stride 64.
template<bool ADD, bool GST>
__device__ __forceinline__ void mm_nn_x2(const float* __restrict__ A,
                                         const float* __restrict__ B,
                                         const float* __restrict__ Add,
                                         float* __restrict__ O,
                                         float* __restrict__ G,
                                         int tid)
{
    const int tx4 = (tid & 15) << 2;
    const int ty4 = (tid >> 4) << 2;
    ull acc[4][2];
    #pragma unroll
    for (int i = 0; i < 4; i++){ acc[i][0] = dup2(0.0f); acc[i][1] = dup2(0.0f); }
    #pragma unroll
    for (int k0 = 0; k0 < 64; k0 += 4){
        float4 a0 = *(const float4*)(A + (ty4+0)*SD + k0);
        float4 a1 = *(const float4*)(A + (ty4+1)*SD + k0);
        float4 a2 = *(const float4*)(A + (ty4+2)*SD + k0);
        float4 a3 = *(const float4*)(A + (ty4+3)*SD + k0);
        ulonglong2 b0 = *(const ulonglong2*)(B + (k0+0)*SD + tx4);
        ulonglong2 b1 = *(const ulonglong2*)(B + (k0+1)*SD + tx4);
        ulonglong2 b2 = *(const ulonglong2*)(B + (k0+2)*SD + tx4);
        ulonglong2 b3 = *(const ulonglong2*)(B + (k0+3)*SD + tx4);
        #pragma unroll
        for (int i = 0; i < 4; i++){
            float4 av = (i==0)?a0:((i==1)?a1:((i==2)?a2:a3));
            ull d;
            d = dup2(av.x); acc[i][0]=fma2(d,b0.x,acc[i][0]); acc[i][1]=fma2(d,b0.y,acc[i][1]);
            d = dup2(av.y); acc[i][0]=fma2(d,b1.x,acc[i][0]); acc[i][1]=fma2(d,b1.y,acc[i][1]);
            d = dup2(av.z); acc[i][0]=fma2(d,b2.x,acc[i][0]); acc[i][1]=fma2(d,b2.y,acc[i][1]);
            d = dup2(av.w); acc[i][0]=fma2(d,b3.x,acc[i][0]); acc[i][1]=fma2(d,b3.y,acc[i][1]);
        }
    }
    #pragma unroll
    for (int i = 0; i < 4; i++){
        ull v0 = acc[i][0], v1 = acc[i][1];
        if (ADD){
            ulonglong2 ad = *(const ulonglong2*)(Add + (ty4+i)*SD + tx4);
            v0 = add2(v0, ad.x); v1 = add2(v1, ad.y);
        }
        ulonglong2 st; st.x = v0; st.y = v1;
        *(ulonglong2*)(O + (ty4+i)*SD + tx4) = st;
        if (GST) *(ulonglong2*)(G + (ty4+i)*64 + tx4) = st;
    }
    __syncthreads();
}

// O = Sub - A^T @ B ; ends synced
__device__ __forceinline__ void mm_tn_sub_x2(const float* __restrict__ A,
                                             const float* __restrict__ B,
                                             const float* __restrict__ Sub,
                                             float* __restrict__ O, int tid)
{
    const int tx4 = (tid & 15) << 2;
    const int ty4 = (tid >> 4) << 2;
    ull acc[4][2];
    #pragma unroll
    for (int i = 0; i < 4; i++){ acc[i][0] = dup2(0.0f); acc[i][1] = dup2(0.0f); }
    #pragma unroll
    for (int k = 0; k < 64; k++){
        float4 av = *(const float4*)(A + k*SD + ty4);
        ulonglong2 bv = *(const ulonglong2*)(B + k*SD + tx4);
        ull d;
        d = dup2(av.x); acc[0][0]=fma2(d,bv.x,acc[0][0]); acc[0][1]=fma2(d,bv.y,acc[0][1]);
        d = dup2(av.y); acc[1][0]=fma2(d,bv.x,acc[1][0]); acc[1][1]=fma2(d,bv.y,acc[1][1]);
        d = dup2(av.z); acc[2][0]=fma2(d,bv.x,acc[2][0]); acc[2][1]=fma2(d,bv.y,acc[2][1]);
        d = dup2(av.w); acc[3][0]=fma2(d,bv.x,acc[3][0]); acc[3][1]=fma2(d,bv.y,acc[3][1]);
    }
    const ull NEG1 = dup2(-1.0f);
    #pragma unroll
    for (int i = 0; i < 4; i++){
        ulonglong2 sv = *(const ulonglong2*)(Sub + (ty4+i)*SD + tx4);
        ulonglong2 st;
        st.x = fma2(NEG1, acc[i][0], sv.x);
        st.y = fma2(NEG1, acc[i][1], sv.y);
        *(ulonglong2*)(O + (ty4+i)*SD + tx4) = st;
    }
    __syncthreads();
}

// ---------------- fused register GJ solve: M X = RHS --------------------
// M symmetric (SPD). Thread (r=tid>>2, cb=(tid&3)*16) holds row r of M in
// m2[8] (f32 pairs) and row r of RHS in r2[8]. On exit r2 = row r of X.
// One __syncthreads per pivot. prow: 2*128 floats (db: [M row | RHS row]).
__device__ __forceinline__ void gj_solve_core(ull* m2, ull* r2,
                                              float* __restrict__ prow,
                                              float* __restrict__ scb,
                                              const int r, const int cb)
{
    #pragma unroll 1
    for (int p = 0; p < 64; p++){
        float* prb = prow + ((p & 1) << 7);
        if (r == p){
            ulonglong2 s;
            s.x=m2[0]; s.y=m2[1]; *(ulonglong2*)(prb + cb)      = s;
            s.x=m2[2]; s.y=m2[3]; *(ulonglong2*)(prb + cb + 4)  = s;
            s.x=m2[4]; s.y=m2[5]; *(ulonglong2*)(prb + cb + 8)  = s;
            s.x=m2[6]; s.y=m2[7]; *(ulonglong2*)(prb + cb + 12) = s;
            s.x=r2[0]; s.y=r2[1]; *(ulonglong2*)(prb + 64 + cb)      = s;
            s.x=r2[2]; s.y=r2[3]; *(ulonglong2*)(prb + 64 + cb + 4)  = s;
            s.x=r2[4]; s.y=r2[5]; *(ulonglong2*)(prb + 64 + cb + 8)  = s;
            s.x=r2[6]; s.y=r2[7]; *(ulonglong2*)(prb + 64 + cb + 12) = s;
            if ((p >> 4) == (cb >> 4)){
                int l = p & 15;
                float2 h = unpk(m2[l >> 1]);
                float pv = (l & 1) ? h.y : h.x;
                scb[p & 1] = pv;
                prb[p] = pv + 1.0f;     // augment pivot row at col p
            }
        }
        __syncthreads();
        const float piv = scb[p & 1];
        const float pivinv = __frcp_rn(piv);
        const float urow = prb[r];      // augmented at r==p
        const float u_ = (r < p) ? -urow : ((r == p) ? urow - 2.0f : urow);
        const ull fd = dup2(-(u_ * pivinv));
        ulonglong2 q0 = *(const ulonglong2*)(prb + cb);
        ulonglong2 q1 = *(const ulonglong2*)(prb + cb + 4);
        ulonglong2 q2 = *(const ulonglong2*)(prb + cb + 8);
        ulonglong2 q3 = *(const ulonglong2*)(prb + cb + 12);
        m2[0]=fma2(fd,q0.x,m2[0]); m2[1]=fma2(fd,q0.y,m2[1]);
        m2[2]=fma2(fd,q1.x,m2[2]); m2[3]=fma2(fd,q1.y,m2[3]);
        m2[4]=fma2(fd,q2.x,m2[4]); m2[5]=fma2(fd,q2.y,m2[5]);
        m2[6]=fma2(fd,q3.x,m2[6]); m2[7]=fma2(fd,q3.y,m2[7]);
        ulonglong2 w0 = *(const ulonglong2*)(prb + 64 + cb);
        ulonglong2 w1 = *(const ulonglong2*)(prb + 64 + cb + 4);
        ulonglong2 w2 = *(const ulonglong2*)(prb + 64 + cb + 8);
        ulonglong2 w3 = *(const ulonglong2*)(prb + 64 + cb + 12);
        r2[0]=fma2(fd,w0.x,r2[0]); r2[1]=fma2(fd,w0.y,r2[1]);
        r2[2]=fma2(fd,w1.x,r2[2]); r2[3]=fma2(fd,w1.y,r2[3]);
        r2[4]=fma2(fd,w2.x,r2[4]); r2[5]=fma2(fd,w2.y,r2[5]);
        r2[6]=fma2(fd,w3.x,r2[6]); r2[7]=fma2(fd,w3.y,r2[7]);
    }
}

// ---------------- kernel 1: Q/R construction ----------------
__global__ void qr_kernel(const float* __restrict__ Lq, const float* __restrict__ Lr){
    __shared__ float sL[64*65];
    const float* L = (blockIdx.x == 0) ? Lq : Lr;
    float* O = (blockIdx.x == 0) ? g_Q : g_R;
    int tid = threadIdx.x;
    for (int i = tid; i < 4096; i += 256) sL[(i>>6)*65 + (i&63)] = L[i];
    __syncthreads();
    for (int e = tid; e < 4096; e += 256){
        int i = e >> 6, j = e & 63;
        float acc = (i == j) ? 1e-3f : 0.0f;
        #pragma unroll 8
        for (int k = 0; k < 64; k++) acc += sL[i*65+k]*sL[j*65+k];
        O[e] = acc;
    }
}

// ---------------- kernel 2: LSTM + softmax weights ----------------
__global__ void __launch_bounds__(128) lstm_kernel(
    const float* __restrict__ x,
    const float* __restrict__ Wih, const float* __restrict__ Whh,
    const float* __restrict__ bih, const float* __restrict__ bhh)
{
    extern __shared__ float sm[];
    float* sWih = sm;                 // 128*65
    float* sWhh = sWih + 128*65;      // 128*33
    float* sx   = sWhh + 128*33;      // 128*64
    float* sh   = sx + 128*64;        // 32
    float* sg   = sh + 32;            // 128
    const int b = blockIdx.x, tid = threadIdx.x;
    for (int i = tid; i < 128*64; i += 128) sWih[(i>>6)*65 + (i&63)] = Wih[i];
    for (int i = tid; i < 128*32; i += 128) sWhh[(i>>5)*33 + (i&31)] = Whh[i];
    for (int i = tid; i < TT*64;  i += 128) sx[i] = x[((i>>6)*BB + b)*64 + (i&63)];
    if (tid < 32) sh[tid] = 0.0f;
    const float bias = bih[tid] + bhh[tid];
    float c = 0.0f;
    __syncthreads();
    for (int t = 0; t < TT; t++){
        float acc = bias;
        const float* wr = sWih + tid*65;
        const float* xr = sx + t*64;
        #pragma unroll 8
        for (int j = 0; j < 64; j++) acc += wr[j]*xr[j];
        const float* hr = sWhh + tid*33;
        #pragma unroll 8
        for (int j = 0; j < 32; j++) acc += hr[j]*sh[j];
        sg[tid] = acc;
        __syncthreads();
        if (tid < 32){
            float ig = 1.0f/(1.0f+expf(-sg[tid]));
            float fg = 1.0f/(1.0f+expf(-sg[32+tid]));
            float gg = tanhf(sg[64+tid]);
            float og = 1.0f/(1.0f+expf(-sg[96+tid]));
            c = fg*c + ig*gg;
            float h = og*tanhf(c);
            sh[tid] = h;
            float m = h;
            for (int o = 16; o; o >>= 1) m = fmaxf(m, __shfl_xor_sync(0xffffffffu, m, o));
            float e = expf(h - m);
            float s = e;
            for (int o = 16; o; o >>= 1) s += __shfl_xor_sync(0xffffffffu, s, o);
            g_w[(t*BB + b)*KK + tid] = e/s;
        }
        __syncthreads();
    }
}

// ---------------- kernel 3: mix A_t, C_t from basis ----------------
__global__ void mix_kernel(const float* __restrict__ AK, const float* __restrict__ CK){
    __shared__ float sB[32*256];
    __shared__ float sw[64*33];
    const int chunk = blockIdx.x;     // 0..15
    const int grp   = blockIdx.y;     // 0..255
    const float* Bsrc = (blockIdx.z == 0) ? AK : CK;
    float* Odst = (blockIdx.z == 0) ? g_A : g_C;
    const int tid = threadIdx.x;      // 256
    for (int i = tid; i < 32*256; i += 256)
        sB[i] = Bsrc[(i>>8)*4096 + chunk*256 + (i&255)];
    for (int i = tid; i < 64*32; i += 256)
        sw[(i>>5)*33 + (i&31)] = g_w[((size_t)grp*64 + (i>>5))*KK + (i&31)];
    __syncthreads();
    const int j = tid;
    for (int tb = 0; tb < 64; tb++){
        float acc = 0.0f;
        const float* wv = sw + tb*33;
        #pragma unroll
        for (int k = 0; k < 32; k++) acc += wv[k]*sB[k*256 + j];
        Odst[(size_t)(grp*64 + tb)*4096 + chunk*256 + j] = acc;
    }
}

// ---------------- kernel 4: Kalman filter (256 threads, 4x4 tiles) --------
__global__ void __launch_bounds__(256, 1) filter_kernel(
    const float* __restrict__ as_,
    const float* __restrict__ init_mean,
    const float* __restrict__ init_cov)
{
    extern __shared__ float sm[];
    float* Qs  = sm;
    float* Rs  = Qs  + 64*SD;
    float* As  = Rs  + 64*SD;
    float* AsT = As  + 64*SD;
    float* Cs  = AsT + 64*SD;
    float* CsT = Cs  + 64*SD;
    float* BP0 = CsT + 64*SD;
    float* BP1 = BP0 + 64*SD;
    float* T1  = BP1 + 64*SD;   // CP, later Acovt
    float* T2  = T1  + 64*SD;   // S, later K^T
    float* T3  = T2  + 64*SD;   // covt
    float* vmean = T3 + 64*SD;
    float* vmt   = vmean + 64;
    float* vmn   = vmt + 64;
    float* vin   = vmn + 64;
    float* vat   = vin + 64;
    float* prow  = vat + 64;    // 256
    float* scb   = prow + 256;  // 2 (+pad)
    const int b = blockIdx.x, tid = threadIdx.x;
    const int r  = tid >> 2;
    const int cb = (tid & 3) << 4;

    for (int i = tid; i < 4096; i += 256){
        int rr = i >> 6, cc = i & 63;
        BP0[rr*SD + cc] = init_cov[i];
        Qs[rr*SD + cc]  = g_Q[i];
        Rs[rr*SD + cc]  = g_R[i];
    }
    // preload t=0 tiles
    {
        const float* gA = g_A + (size_t)b*4096;
        const float* gC = g_C + (size_t)b*4096;
        for (int i4 = tid; i4 < 1024; i4 += 256){
            int rr = i4 >> 4, c4 = (i4 & 15) << 2;
            float4 va = *(const float4*)(gA + rr*64 + c4);
            float4 vc = *(const float4*)(gC + rr*64 + c4);
            *(float4*)(As + rr*SD + c4) = va;
            *(float4*)(Cs + rr*SD + c4) = vc;
            AsT[(c4+0)*SD + rr] = va.x; AsT[(c4+1)*SD + rr] = va.y;
            AsT[(c4+2)*SD + rr] = va.z; AsT[(c4+3)*SD + rr] = va.w;
            CsT[(c4+0)*SD + rr] = vc.x; CsT[(c4+1)*SD + rr] = vc.y;
            CsT[(c4+2)*SD + rr] = vc.z; CsT[(c4+3)*SD + rr] = vc.w;
        }
        if (tid < 64){
            vat[tid]   = as_[(size_t)b*64 + tid];
            vmean[tid] = init_mean[tid];
        }
    }
    __syncthreads();

    float* P  = BP0;
    float* Pn = BP1;

    for (int t = 0; t < TT; t++){
        const int tb = t*BB + b;

        mm_nn_x2<false,false>(Cs, P, 0, T1, 0, tid);   // T1 = CP
        mm_nn_x2<true ,false>(T1, CsT, Rs, T2, 0, tid);// T2 = S = CP C^T + R

        if (tid < 64){                                 // vin = a_t - C mean_p
            float acc = 0.0f;
            #pragma unroll 8
            for (int j = 0; j < 64; j++) acc += Cs[tid*SD + j]*vmean[j];
            vin[tid] = vat[tid] - acc;
        }

        // fused solve: K^T = S^-1 CP
        {
            ull m2[8], r2[8];
            #pragma unroll
            for (int u = 0; u < 4; u++){
                ulonglong2 a = *(const ulonglong2*)(T2 + r*SD + cb + 4*u);
                m2[2*u] = a.x; m2[2*u+1] = a.y;
                ulonglong2 c = *(const ulonglong2*)(T1 + r*SD + cb + 4*u);
                r2[2*u] = c.x; r2[2*u+1] = c.y;
            }
            gj_solve_core(m2, r2, prow, scb, r, cb);
            #pragma unroll
            for (int u = 0; u < 4; u++){
                ulonglong2 s; s.x = r2[2*u]; s.y = r2[2*u+1];
                *(ulonglong2*)(T2 + r*SD + cb + 4*u) = s;  // T2 = K^T
            }
            __syncthreads();
        }

        if (tid < 64){                                 // mean_t = mean_p + K^T^T vin
            float acc = vmean[tid];
            #pragma unroll 8
            for (int j = 0; j < 64; j++) acc += T2[j*SD + tid]*vin[j];
            vmt[tid] = acc;
            g_fm[(size_t)tb*64 + tid] = acc;
        }

        mm_tn_sub_x2(T2, T1, P, T3, tid);              // T3 = covt = P - K^T^T CP

        // prefetch next step's A/C tiles + a_{t+1} into registers
        float4 pfA[4], pfC[4]; float pfa = 0.0f;
        if (t + 1 < TT){
            const float* gA = g_A + (size_t)(tb + BB)*4096;
            const float* gC = g_C + (size_t)(tb + BB)*4096;
            #pragma unroll
            for (int u = 0; u < 4; u++){
                int i4 = tid + 256*u;
                int rr = i4 >> 4, c4 = (i4 & 15) << 2;
                pfA[u] = *(const float4*)(gA + rr*64 + c4);
                pfC[u] = *(const float4*)(gC + rr*64 + c4);
            }
            if (tid < 64) pfa = as_[(size_t)(tb + BB)*64 + tid];
        }

        mm_nn_x2<false,true>(As, T3, 0, T1,            // T1 = A covt (+ gmem)
                             g_AC + (size_t)tb*4096, tid);

        if (tid < 64){                                 // mean_n = A mean_t
            float acc = 0.0f;
            #pragma unroll 8
            for (int j = 0; j < 64; j++) acc += As[tid*SD + j]*vmt[j];
            vmn[tid] = acc;
            if (t == 0) g_mp0[b*64 + tid] = acc;
        }

        mm_nn_x2<true,true>(T1, AsT, Qs, Pn,           // Pn = A covt A^T + Q (+ gmem)
                            g_Pn + (size_t)tb*4096, tid);

        if (tid < 64) vmean[tid] = vmn[tid];           // same-thread write/read
        float* tmp = P; P = Pn; Pn = tmp;

        if (t + 1 < TT){                               // commit prefetched tiles
            #pragma unroll
            for (int u = 0; u < 4; u++){
                int i4 = tid + 256*u;
                int rr = i4 >> 4, c4 = (i4 & 15) << 2;
                float4 va = pfA[u], vc = pfC[u];
                *(float4*)(As + rr*SD + c4) = va;
                *(float4*)(Cs + rr*SD + c4) = vc;
                AsT[(c4+0)*SD + rr] = va.x; AsT[(c4+1)*SD + rr] = va.y;
                AsT[(c4+2)*SD + rr] = va.z; AsT[(c4+3)*SD + rr] = va.w;
                CsT[(c4+0)*SD + rr] = vc.x; CsT[(c4+1)*SD + rr] = vc.y;
                CsT[(c4+2)*SD + rr] = vc.z; CsT[(c4+3)*SD + rr] = vc.w;
            }
            if (tid < 64) vat[tid] = pfa;
        }
        __syncthreads();
    }
}

// ---------------- kernel 5: Pn^-1, ONE PROBLEM PER WARP ------------------
// Lane l holds rows l and l+32 (64 ull regs, static indexing only).
// Per pivot: owner lane writes its augmented row to a parity-double-buffered
// 64-float smem strip, ONE __syncwarp, broadcast LDS + 64 fma2. No block
// barriers -> 8 independent problems per SM interleave freely.
__global__ void __launch_bounds__(128, 2) jinv_kernel(){
    __shared__ float sprow[4][2][68];
    const int tid = threadIdx.x;
    const int w = tid >> 5, l = tid & 31;
    const int tb = blockIdx.x*4 + w;
    const float* gPn = g_Pn + (size_t)tb*4096;

    ull m0[32], m1[32];
    #pragma unroll
    for (int j = 0; j < 16; j++){
        ulonglong2 a = *(const ulonglong2*)(gPn + l*64 + 4*j);
        m0[2*j] = a.x; m0[2*j+1] = a.y;
        ulonglong2 b = *(const ulonglong2*)(gPn + (l+32)*64 + 4*j);
        m1[2*j] = b.x; m1[2*j+1] = b.y;
    }

    #pragma unroll 1
    for (int p = 0; p < 64; p++){
        float* prb = sprow[w][p & 1];
        if (l == (p & 31)){
            if (p < 32){
                #pragma unroll
                for (int j = 0; j < 16; j++){
                    ulonglong2 s; s.x = m0[2*j]; s.y = m0[2*j+1];
                    *(ulonglong2*)(prb + 4*j) = s;
                }
            } else {
                #pragma unroll
                for (int j = 0; j < 16; j++){
                    ulonglong2 s; s.x = m1[2*j]; s.y = m1[2*j+1];
                    *(ulonglong2*)(prb + 4*j) = s;
                }
            }
            prb[p] = prb[p] + 1.0f;      // augment pivot row at col p
        }
        __syncwarp();
        const float piv = prb[p] - 1.0f;
        const float pivinv = __frcp_rn(piv);
        float u0 = prb[l];
        u0 = (l < p) ? -u0 : ((l == p) ? u0 - 2.0f : u0);
        const int r1 = l + 32;
        float u1 = prb[r1];
        u1 = (r1 < p) ? -u1 : ((r1 == p) ? u1 - 2.0f : u1);
        const ull fd0 = dup2(-(u0 * pivinv));
        const ull fd1 = dup2(-(u1 * pivinv));
        #pragma unroll
        for (int j = 0; j < 16; j++){
            ulonglong2 q = *(const ulonglong2*)(prb + 4*j);
            m0[2*j]   = fma2(fd0, q.x, m0[2*j]);
            m0[2*j+1] = fma2(fd0, q.y, m0[2*j+1]);
            m1[2*j]   = fma2(fd1, q.x, m1[2*j]);
            m1[2*j+1] = fma2(fd1, q.y, m1[2*j+1]);
        }
    }

    float* gJ = g_J + (size_t)tb*4096;
    #pragma unroll
    for (int j = 0; j < 16; j++){
        ulonglong2 s;
        s.x = m0[2*j]; s.y = m0[2*j+1];
        *(ulonglong2*)(gJ + l*64 + 4*j) = s;
        s.x = m1[2*j]; s.y = m1[2*j+1];
        *(ulonglong2*)(gJ + (l+32)*64 + 4*j) = s;
    }
}

// ---------------- kernel 6: RTS smoother, matrix-free J ------------------
__global__ void __launch_bounds__(256) smooth_kernel(float* __restrict__ out)
{
    __shared__ float sP[64*65];   // Pn^-1
    __shared__ float sA[64*65];   // A covt
    __shared__ float sv[64];
    __shared__ float sy[64];
    __shared__ float sms[64];
    __shared__ float smp0[64];
    const int b = blockIdx.x, tid = threadIdx.x;

    if (tid < 64){
        float m = g_fm[(size_t)((TT-1)*BB + b)*64 + tid];
        sms[tid] = m;
        out[(size_t)((TT-1)*BB + b)*64 + tid] = m;
        smp0[tid] = g_mp0[b*64 + tid];
    }
    float4 rp[4], ra[4];
    {
        const float* gP = g_J  + (size_t)((TT-2)*BB + b)*4096;
        const float* gA = g_AC + (size_t)((TT-2)*BB + b)*4096;
        #pragma unroll
        for (int u = 0; u < 4; u++){
            rp[u] = *(const float4*)(gP + (size_t)(tid + 256*u)*4);
            ra[u] = *(const float4*)(gA + (size_t)(tid + 256*u)*4);
        }
    }
    __syncthreads();

    for (int t = TT-2; t >= 0; t--){
        #pragma unroll
        for (int u = 0; u < 4; u++){
            int idx = tid + 256*u;
            int row = idx >> 4, c4 = (idx & 15) << 2;
            sP[row*65 + c4 + 0] = rp[u].x;
            sP[row*65 + c4 + 1] = rp[u].y;
            sP[row*65 + c4 + 2] = rp[u].z;
            sP[row*65 + c4 + 3] = rp[u].w;
            sA[row*65 + c4 + 0] = ra[u].x;
            sA[row*65 + c4 + 1] = ra[u].y;
            sA[row*65 + c4 + 2] = ra[u].z;
            sA[row*65 + c4 + 3] = ra[u].w;
        }
        if (tid < 64) sv[tid] = sms[tid] - smp0[tid];
        __syncthreads();
        if (t > 0){
            const float* gP = g_J  + (size_t)((t-1)*BB + b)*4096;
            const float* gA = g_AC + (size_t)((t-1)*BB + b)*4096;
            #pragma unroll
            for (int u = 0; u < 4; u++){
                rp[u] = *(const float4*)(gP + (size_t)(tid + 256*u)*4);
                ra[u] = *(const float4*)(gA + (size_t)(tid + 256*u)*4);
            }
        }
        if (tid < 64){                       // y = Pn^-1 v
            float acc = 0.0f;
            #pragma unroll 8
            for (int j = 0; j < 64; j++) acc += sP[tid*65 + j]*sv[j];
            sy[tid] = acc;
        }
        __syncthreads();
        if (tid < 64){                       // s = fm + (A covt)^T y
            float acc = g_fm[(size_t)(t*BB + b)*64 + tid];
            #pragma unroll 8
            for (int j = 0; j < 64; j++) acc += sA[j*65 + tid]*sy[j];
            out[(size_t)(t*BB + b)*64 + tid] = acc;
            sms[tid] = acc;
        }
        __syncthreads();
    }
}

// ---------------- launch ----------------
extern "C" void kernel_launch(void* const* d_in, const int* in_sizes, int n_in,
                              void* d_out, int out_size)
{
    const float* as_ = (const float*)d_in[0];
    const float* AK  = (const float*)d_in[1];
    const float* CK  = (const float*)d_in[2];
    const float* Lq  = (const float*)d_in[3];
    const float* Lr  = (const float*)d_in[4];
    const float* Wih = (const float*)d_in[5];
    const float* Whh = (const float*)d_in[6];
    const float* bih = (const float*)d_in[7];
    const float* bhh = (const float*)d_in[8];
    const float* im  = (const float*)d_in[9];
    const float* ic  = (const float*)d_in[10];
    float* out = (float*)d_out;

    const int lstm_smem = (128*65 + 128*33 + 128*64 + 32 + 128)*4;
    const int filt_smem = (11*64*SD + 5*64 + 256 + 8)*4;
    cudaFuncSetAttribute(lstm_kernel,   cudaFuncAttributeMaxDynamicSharedMemorySize, lstm_smem);
    cudaFuncSetAttribute(filter_kernel, cudaFuncAttributeMaxDynamicSharedMemorySize, filt_smem);

    qr_kernel<<<2, 256>>>(Lq, Lr);
    lstm_kernel<<<BB, 128, lstm_smem>>>(as_, Wih, Whh, bih, bhh);
    mix_kernel<<<dim3(16, 256, 2), 256>>>(AK, CK);
    filter_kernel<<<BB, 256, filt_smem>>>(as_, im, ic);
    jinv_kernel<<<((TT-1)*BB)/4, 128>>>();
    smooth_kernel<<<BB, 256>>>(out);
}